// round 9
// baseline (speedup 1.0000x reference)
#include <cuda_runtime.h>
#include <cuda_bf16.h>
#include <cstdint>

// ---------------------------------------------------------------------------
// GIFNeuron: h = x @ W^T + b  (M=32768, N=512, K=512, fp32)
// GEMM: scalar fp32 FFMA, sequential-k fma order (bit-exact vs reference,
// at fp32 datapath peak ~41 TF/s -> ~415us, pinned).
// Scan: 28-cyc/step fast path (rcp predicted one step ahead, off-chain)
// with exact residual guards + bit-exact redo.
// Outputs flattened: spikes [B,T,H] | v_f [B,H] | theta_f [B,H]
// ---------------------------------------------------------------------------

#define M_DIM 32768   // B*T
#define N_DIM 512     // H
#define K_DIM 512     // IN
#define B_DIM 16
#define T_DIM 2048

// 64 MB scratch for h (static __device__ array: allocation-free)
__device__ float g_h[(size_t)M_DIM * N_DIM];

// ---------------------------------------------------------------------------
// Kernel 1: fp32 GEMM (verbatim round-1: bit-exact, datapath-peak bound)
// ---------------------------------------------------------------------------
#define BM 128
#define BN 128
#define BK 16
#define TM 8
#define TN 8

__global__ __launch_bounds__(256, 2)
void gemm_nt_kernel(const float* __restrict__ A,
                    const float* __restrict__ B,
                    const float* __restrict__ bias,
                    float* __restrict__ C)
{
    __shared__ float As[BK][BM];
    __shared__ float Bs[BK][BN];

    const int bm  = blockIdx.y * BM;
    const int bn  = blockIdx.x * BN;
    const int tid = threadIdx.x;

    const int tr = (tid >> 4) * TM;
    const int tc = (tid & 15) * TN;

    float acc[TM][TN];
#pragma unroll
    for (int i = 0; i < TM; i++)
#pragma unroll
        for (int j = 0; j < TN; j++)
            acc[i][j] = 0.0f;

    const float* Ab = A + (size_t)bm * K_DIM;
    const float* Bb = B + (size_t)bn * K_DIM;

    for (int k0 = 0; k0 < K_DIM; k0 += BK) {
#pragma unroll
        for (int i = 0; i < 2; i++) {
            int idx = tid + i * 256;
            int row = idx >> 2;
            int kq  = (idx & 3) << 2;
            float4 av = *(const float4*)(Ab + (size_t)row * K_DIM + k0 + kq);
            As[kq + 0][row] = av.x;
            As[kq + 1][row] = av.y;
            As[kq + 2][row] = av.z;
            As[kq + 3][row] = av.w;
            float4 bv = *(const float4*)(Bb + (size_t)row * K_DIM + k0 + kq);
            Bs[kq + 0][row] = bv.x;
            Bs[kq + 1][row] = bv.y;
            Bs[kq + 2][row] = bv.z;
            Bs[kq + 3][row] = bv.w;
        }
        __syncthreads();

#pragma unroll
        for (int kk = 0; kk < BK; kk++) {
            float ar[TM], br[TN];
#pragma unroll
            for (int i = 0; i < TM; i++) ar[i] = As[kk][tr + i];
#pragma unroll
            for (int j = 0; j < TN; j++) br[j] = Bs[kk][tc + j];
#pragma unroll
            for (int i = 0; i < TM; i++)
#pragma unroll
                for (int j = 0; j < TN; j++)
                    acc[i][j] = fmaf(ar[i], br[j], acc[i][j]);
        }
        __syncthreads();
    }

#pragma unroll
    for (int i = 0; i < TM; i++) {
        size_t crow = (size_t)(bm + tr + i) * N_DIM + bn + tc;
#pragma unroll
        for (int j = 0; j < TN; j += 4) {
            float4 o;
            o.x = acc[i][j + 0] + bias[bn + tc + j + 0];
            o.y = acc[i][j + 1] + bias[bn + tc + j + 1];
            o.z = acc[i][j + 2] + bias[bn + tc + j + 2];
            o.w = acc[i][j + 3] + bias[bn + tc + j + 3];
            *(float4*)(C + crow + j) = o;
        }
    }
}

// ---------------------------------------------------------------------------
// Kernel 2: GIF scan. One thread per (b,h): 8192 threads = 128 blocks x 64.
//
// Per-step critical cycle (28 cyc):
//   d_prev -> vin = fma(v,DECAY,in) -> qm = fma(vin,r,-0.499999)
//   -> qc = max(qm,-0.25) -> +MAGIC -> -MAGIC = s -> d = fma(-s,theta,vin)
// r is a one-fma predictor: r = rc_prev - s_prev*m_prev, where
// rc = rcp.approx(0.99*theta+0.01) and m = 0.01*rc^2 are computed one step
// ahead (rcp's 16-cyc MUFU latency fully hidden off the cycle).
//
// Exact guards (fire => bit-exact redo of the 16-step block):
//   g1: vin < -32*theta            (negative clamp would engage)
//   g2: s > 16.5                   (clip engages; also covers positive clamp)
//   g3: d<0 && s>0                 (s one too big; exact fma sign)
//   g4: d >= theta*(1-2e-6)        (s too small OR RN-division boundary)
// Accepted steps provably equal reference floor(RN(v/theta)) semantics.
// ---------------------------------------------------------------------------
__global__ __launch_bounds__(64)
void gif_scan_kernel(float* __restrict__ spikes,
                     float* __restrict__ v_out,
                     float* __restrict__ theta_out)
{
    const int idx = blockIdx.x * 64 + threadIdx.x;
    if (idx >= B_DIM * N_DIM) return;
    const int b  = idx >> 9;
    const int hh = idx & 511;

    const float* hp = g_h    + (size_t)b * T_DIM * N_DIM + hh;
    float*       sp = spikes + (size_t)b * T_DIM * N_DIM + hh;

    const float DECAY = 0.90483741803595952f;   // exp(-1/10)
    const float MAGIC = 12582912.0f;            // 2^23 + 2^22

    float v = 0.0f;
    float theta = 1.0f;
    float sp_ = 0.0f;     // previous spike
    float rc_ = 1.0f;     // rcp(predicted theta base); theta0 = 1 -> 1.0
    float m_  = 0.0f;     // 0.01*rc^2 correction slope

    float cur[16];
#pragma unroll
    for (int u = 0; u < 16; u++)
        cur[u] = hp[(size_t)u * N_DIM];

    for (int t0 = 0; t0 < T_DIM; t0 += 16) {
        float nxt[16];
        if (t0 + 16 < T_DIM) {
#pragma unroll
            for (int u = 0; u < 16; u++)
                nxt[u] = hp[(size_t)(t0 + 16 + u) * N_DIM];
        } else {
#pragma unroll
            for (int u = 0; u < 16; u++)
                nxt[u] = 0.0f;
        }

        const float v_save  = v;
        const float th_save = theta;
        float out[16];
        float bad = -1.0f;

#pragma unroll
        for (int u = 0; u < 16; u++) {
            float vin = fmaf(v, DECAY, cur[u]);               // chain
            float r   = fmaf(-sp_, m_, rc_);                  // 1-fma 1/theta predictor
            float qm  = fmaf(vin, r, -0.499999f);             // chain
            float qc  = fmaxf(qm, -0.25f);                    // chain
            float t1  = __fadd_rn(qc, MAGIC);                 // chain
            float s   = __fsub_rn(t1, MAGIC);                 // chain: integer >= 0
            float d   = fmaf(-s, theta, vin);                 // chain -> next v

            // guards (off-chain)
            bad = fmaxf(bad, fmaf(-32.0f, theta, -vin));      // g1
            bad = fmaxf(bad, s - 16.5f);                      // g2
            bad = fmaxf(bad, fminf(-d, s - 0.5f));            // g3
            bad = fmaxf(bad, fmaf(-0.999998f, theta, d));     // g4

            // next-step reciprocal prediction (off-chain; rcp hidden)
            float c  = fmaf(0.99f, theta, 0.01f);
            float rc;
            asm("rcp.approx.f32 %0, %1;" : "=f"(rc) : "f"(c));
            float m  = 0.01f * rc * rc;

            v = d;
            theta = theta + 0.01f * s - 0.01f * (theta - 1.0f);  // exact ref order
            sp_ = s; rc_ = rc; m_ = m;
            out[u] = s;
        }

        if (__builtin_expect(bad >= 0.0f, 0)) {
            // Exact reference-semantics redo (verbatim round-1 step code)
            v = v_save;
            theta = th_save;
#pragma unroll
            for (int u = 0; u < 16; u++) {
                v = fmaf(v, DECAY, cur[u]);
                float cl = 32.0f * theta;
                v = fminf(fmaxf(v, -cl), cl);
                float s = floorf(v / theta);
                s = fminf(fmaxf(s, 0.0f), 16.0f);
                v = fmaf(-s, theta, v);
                theta = theta + 0.01f * s - 0.01f * (theta - 1.0f);
                out[u] = s;
            }
            // reset predictor directly from exact state
            sp_ = 0.0f; m_ = 0.0f;
            asm("rcp.approx.f32 %0, %1;" : "=f"(rc_) : "f"(theta));
        }

#pragma unroll
        for (int u = 0; u < 16; u++)
            sp[(size_t)(t0 + u) * N_DIM] = out[u];

#pragma unroll
        for (int u = 0; u < 16; u++)
            cur[u] = nxt[u];
    }

    v_out[idx]     = v;
    theta_out[idx] = theta;
}

// ---------------------------------------------------------------------------
// kernel_launch
// Inputs (metadata order): x [16,2048,512] f32, W [512,512] f32, b [512] f32
// Output: float32, spikes | v_f | theta_f
// ---------------------------------------------------------------------------
extern "C" void kernel_launch(void* const* d_in, const int* in_sizes, int n_in,
                              void* d_out, int out_size)
{
    const float* x = (const float*)d_in[0];
    const float* W = (const float*)d_in[1];
    const float* b = (const float*)d_in[2];

    float* out    = (float*)d_out;
    float* spikes = out;
    float* v_f    = out + (size_t)B_DIM * T_DIM * N_DIM;
    float* th_f   = v_f + (size_t)B_DIM * N_DIM;

    float* h;
    cudaGetSymbolAddress((void**)&h, g_h);

    dim3 gemm_grid(N_DIM / BN, M_DIM / BM);   // (4, 256)
    gemm_nt_kernel<<<gemm_grid, 256>>>(x, W, b, h);

    gif_scan_kernel<<<B_DIM * N_DIM / 64, 64>>>(spikes, v_f, th_f);
}